// round 7
// baseline (speedup 1.0000x reference)
#include <cuda_runtime.h>
#include <math.h>
#include <stdint.h>

// ---------------------------------------------------------------------------
// Problem constants
// ---------------------------------------------------------------------------
namespace {
constexpr int B_  = 2;
constexpr int N_  = 512;
constexpr int D_  = 128;   // DIM
constexpr int PH_ = 64;    // POS_HID
constexpr int AH_ = 512;   // ATTN_HID
constexpr int K_  = 16;    // K_NEIGH
constexpr int M1  = B_ * N_;    // 1024
constexpr int M2  = M1 * K_;    // 16384
constexpr int NC_ = AH_ + D_;   // 640 combined cols of the AP gemm
}

// ---------------------------------------------------------------------------
// Scratch
// ---------------------------------------------------------------------------
__device__ float g_qkv[M1 * 3 * D_];
__device__ int   g_idx[M1 * K_];
__device__ float g_hid[M2 * PH_];
__device__ float g_QK [2 * M1 * AH_];   // rows 0..1023 = q@aw1, 1024..2047 = k@aw1
__device__ float g_Wc [PH_ * NC_];      // [pw2@aw1 | pw2]
__device__ float g_bc [NC_];            // [pb2@aw1 + ab1 | pb2]
__device__ float g_PE [M2 * D_];
__device__ float g_A  [M2 * AH_];
__device__ float g_SIM[M2 * D_];

// ---------------------------------------------------------------------------
// 1) qkv = x^T @ w_qkv
// ---------------------------------------------------------------------------
__global__ void qkv_kernel(const float* __restrict__ x, const float* __restrict__ w) {
    __shared__ float sx[D_];
    const int m = blockIdx.x;
    const int b = m >> 9;
    const int n = m & (N_ - 1);
    const int tid = threadIdx.x;   // 128
    sx[tid] = x[b * D_ * N_ + tid * N_ + n];
    __syncthreads();
    float a0 = 0.f, a1 = 0.f, a2 = 0.f;
#pragma unroll 8
    for (int d = 0; d < D_; ++d) {
        const float xv = sx[d];
        const float* wr = w + d * (3 * D_);
        a0 = fmaf(xv, wr[tid],           a0);
        a1 = fmaf(xv, wr[tid + D_],      a1);
        a2 = fmaf(xv, wr[tid + 2 * D_],  a2);
    }
    float* o = g_qkv + m * (3 * D_);
    o[tid] = a0; o[tid + D_] = a1; o[tid + 2 * D_] = a2;
}

// ---------------------------------------------------------------------------
// 2) KNN (exact fp32)
// ---------------------------------------------------------------------------
__global__ void knn_kernel(const float* __restrict__ pos) {
    __shared__ float sx[N_], sy[N_], sz[N_];
    const int lane = threadIdx.x & 31;
    const int warp = threadIdx.x >> 5;
    const int m0 = blockIdx.x * 8;
    const int b = m0 >> 9;

    for (int t = threadIdx.x; t < N_; t += blockDim.x) {
        const float* p = pos + (size_t)(b * N_ + t) * 3;
        sx[t] = p[0]; sy[t] = p[1]; sz[t] = p[2];
    }
    __syncthreads();

    const int m = m0 + warp;
    const int i = m & (N_ - 1);
    const float px = sx[i], py = sy[i], pz = sz[i];

    float d2[16];
#pragma unroll
    for (int t = 0; t < 16; ++t) {
        const int j = lane + 32 * t;
        const float dx = px - sx[j], dy = py - sy[j], dz = pz - sz[j];
        d2[t] = dx * dx + dy * dy + dz * dz;
    }

    unsigned taken = 0u;
    for (int it = 0; it < K_; ++it) {
        float best = 3.4e38f;
        int bt = -1;
#pragma unroll
        for (int t = 0; t < 16; ++t) {
            if (!((taken >> t) & 1u) && d2[t] < best) { best = d2[t]; bt = t; }
        }
        int bj = (bt < 0) ? 0x7fffffff : (lane + 32 * bt);
#pragma unroll
        for (int off = 16; off; off >>= 1) {
            const float ov = __shfl_xor_sync(0xffffffffu, best, off);
            const int   oj = __shfl_xor_sync(0xffffffffu, bj,   off);
            if (ov < best || (ov == best && oj < bj)) { best = ov; bj = oj; }
        }
        if ((bj & 31) == lane) taken |= 1u << (bj >> 5);
        if (lane == 0) g_idx[m * K_ + it] = bj;
    }
}

// ---------------------------------------------------------------------------
// 3) hid = relu(rel_pos @ pw1 + pb1)
// ---------------------------------------------------------------------------
__global__ void hid_kernel(const float* __restrict__ pos,
                           const float* __restrict__ pw1, const float* __restrict__ pb1) {
    const int m = blockIdx.x;
    const int b = m >> 9;
    const int i = m & (N_ - 1);
    const int tid = threadIdx.x;   // 128 = 2 kk x 64 h
    const int h = tid & 63;
    __shared__ float sp[3];
    if (tid < 3) sp[tid] = pos[(size_t)(b * N_ + i) * 3 + tid];
    __syncthreads();
    const float w0 = pw1[h], w1 = pw1[64 + h], w2 = pw1[128 + h], bb = pb1[h];
#pragma unroll
    for (int kp = 0; kp < 8; ++kp) {
        const int kk = kp * 2 + (tid >> 6);
        const int j = g_idx[m * K_ + kk];
        const float* pj = pos + (size_t)(b * N_ + j) * 3;
        const float rx = sp[0] - pj[0], ry = sp[1] - pj[1], rz = sp[2] - pj[2];
        float v = fmaf(rx, w0, fmaf(ry, w1, fmaf(rz, w2, bb)));
        g_hid[(size_t)(m * K_ + kk) * PH_ + h] = fmaxf(v, 0.f);
    }
}

// ---------------------------------------------------------------------------
// 4) prep_w: Wc = [pw2@aw1 | pw2],  bc = [pb2@aw1 + ab1 | pb2]   (fp32)
// ---------------------------------------------------------------------------
__global__ void prep_w_kernel(const float* __restrict__ pw2, const float* __restrict__ pb2,
                              const float* __restrict__ aw1, const float* __restrict__ ab1) {
    const int t = blockIdx.x * blockDim.x + threadIdx.x;
    if (t < PH_ * AH_) {                       // W1c = pw2 @ aw1
        const int h = t >> 9, c = t & (AH_ - 1);
        float s = 0.f;
#pragma unroll 8
        for (int d = 0; d < D_; ++d) s = fmaf(pw2[h * D_ + d], aw1[d * AH_ + c], s);
        g_Wc[h * NC_ + c] = s;
    } else if (t < PH_ * NC_) {                // copy pw2 into cols 512..639
        const int u = t - PH_ * AH_;
        const int h = u >> 7, d = u & (D_ - 1);
        g_Wc[h * NC_ + AH_ + d] = pw2[h * D_ + d];
    } else if (t < PH_ * NC_ + NC_) {          // bias
        const int c = t - PH_ * NC_;
        if (c < AH_) {
            float s = ab1[c];
#pragma unroll 8
            for (int d = 0; d < D_; ++d) s = fmaf(pb2[d], aw1[d * AH_ + c], s);
            g_bc[c] = s;
        } else {
            g_bc[c] = pb2[c - AH_];
        }
    }
}

// ---------------------------------------------------------------------------
// Tensor-core tf32 GEMM (R3 layout, double-buffered). MODE:
//   0 = plain:  C = [bias +] A@W                (A row stride = K)
//   1 = QK:     A rows come from g_qkv: row r<1024 -> q row r; r>=1024 -> k row
//   2 = AP:     W = g_Wc (ld NC_); cols <512 -> g_A with QA-KA gather + relu,
//               cols >=512 -> g_PE plain store.
// ---------------------------------------------------------------------------
__device__ __forceinline__ uint32_t f2tf32(float f) {
    uint32_t u;
    asm("cvt.rna.tf32.f32 %0, %1;" : "=r"(u) : "f"(f));
    return u;
}

__device__ __forceinline__ void mma_tf32(float c[4],
                                         uint32_t a0, uint32_t a1, uint32_t a2, uint32_t a3,
                                         uint32_t b0, uint32_t b1) {
    asm volatile(
        "mma.sync.aligned.m16n8k8.row.col.f32.tf32.tf32.f32 "
        "{%0,%1,%2,%3}, {%4,%5,%6,%7}, {%8,%9}, {%0,%1,%2,%3};"
        : "+f"(c[0]), "+f"(c[1]), "+f"(c[2]), "+f"(c[3])
        : "r"(a0), "r"(a1), "r"(a2), "r"(a3), "r"(b0), "r"(b1));
}

template <int MODE, bool HASBIAS>
__global__ __launch_bounds__(256)
void tc_gemm(const float* __restrict__ A, const float* __restrict__ W,
             const float* __restrict__ bias, float* __restrict__ C,
             float* __restrict__ C2, int M, int N, int K) {
    __shared__ uint32_t As[2][128][36];
    __shared__ uint32_t Bs[2][32][136];

    const int tid  = threadIdx.x;
    const int lane = tid & 31;
    const int warp = tid >> 5;
    const int wm = (warp >> 2) * 64;
    const int wn = (warp & 3) * 32;
    const int m0 = blockIdx.y * 128;
    const int n0 = blockIdx.x * 128;

    float acc[4][4][4];
#pragma unroll
    for (int mi = 0; mi < 4; ++mi)
#pragma unroll
        for (int ni = 0; ni < 4; ++ni)
#pragma unroll
            for (int e = 0; e < 4; ++e) acc[mi][ni][e] = 0.f;

    auto stage = [&](int k0, int buf) {
#pragma unroll
        for (int t = 0; t < 4; ++t) {
            const int idx = tid + t * 256;
            const int r = idx >> 3, c = (idx & 7) << 2;
            float4 v;
            if (MODE == 1) {
                const int qrow = m0 + r;     // 0..2047
                const size_t base = (size_t)(qrow & (M1 - 1)) * 384 + ((qrow >> 10) << 7);
                v = *(const float4*)(A + base + k0 + c);
            } else {
                v = *(const float4*)(A + (size_t)(m0 + r) * K + k0 + c);
            }
            As[buf][r][c + 0] = f2tf32(v.x); As[buf][r][c + 1] = f2tf32(v.y);
            As[buf][r][c + 2] = f2tf32(v.z); As[buf][r][c + 3] = f2tf32(v.w);
        }
#pragma unroll
        for (int t = 0; t < 4; ++t) {
            const int idx = tid + t * 256;
            const int kr = idx >> 5, nc = (idx & 31) << 2;
            const float4 v = *(const float4*)(W + (size_t)(k0 + kr) * N + n0 + nc);
            Bs[buf][kr][nc + 0] = f2tf32(v.x); Bs[buf][kr][nc + 1] = f2tf32(v.y);
            Bs[buf][kr][nc + 2] = f2tf32(v.z); Bs[buf][kr][nc + 3] = f2tf32(v.w);
        }
    };

    auto mmatile = [&](int buf) {
#pragma unroll
        for (int ks = 0; ks < 4; ++ks) {
            const int kk = ks * 8;
            uint32_t af[4][4], bf[4][2];
#pragma unroll
            for (int mi = 0; mi < 4; ++mi) {
                const int rb = wm + mi * 16 + (lane >> 2);
                const int cb = kk + (lane & 3);
                af[mi][0] = As[buf][rb    ][cb    ];
                af[mi][1] = As[buf][rb + 8][cb    ];
                af[mi][2] = As[buf][rb    ][cb + 4];
                af[mi][3] = As[buf][rb + 8][cb + 4];
            }
#pragma unroll
            for (int ni = 0; ni < 4; ++ni) {
                const int nb = wn + ni * 8 + (lane >> 2);
                bf[ni][0] = Bs[buf][kk +     (lane & 3)][nb];
                bf[ni][1] = Bs[buf][kk + 4 + (lane & 3)][nb];
            }
#pragma unroll
            for (int mi = 0; mi < 4; ++mi)
#pragma unroll
                for (int ni = 0; ni < 4; ++ni)
                    mma_tf32(acc[mi][ni], af[mi][0], af[mi][1], af[mi][2], af[mi][3],
                             bf[ni][0], bf[ni][1]);
        }
    };

    const int T = K >> 5;
    stage(0, 0);
    __syncthreads();
    for (int t = 0; t < T; ++t) {
        if (t + 1 < T) stage((t + 1) << 5, (t + 1) & 1);
        mmatile(t & 1);
        __syncthreads();
    }

    // ---- epilogue ----
#pragma unroll
    for (int mi = 0; mi < 4; ++mi) {
        const int r0 = m0 + wm + mi * 16 + (lane >> 2);
#pragma unroll
        for (int ni = 0; ni < 4; ++ni) {
            const int c0 = n0 + wn + ni * 8 + ((lane & 3) << 1);
            const float bv0 = HASBIAS ? bias[c0]     : 0.f;
            const float bv1 = HASBIAS ? bias[c0 + 1] : 0.f;
            float v0 = acc[mi][ni][0] + bv0;
            float v1 = acc[mi][ni][1] + bv1;
            float v2 = acc[mi][ni][2] + bv0;
            float v3 = acc[mi][ni][3] + bv1;
            if (MODE == 2) {
                if (n0 < AH_) {
                    // A-part: add QA_i - KA_j, relu, store g_A (ld=AH_)
#pragma unroll
                    for (int rr = 0; rr < 2; ++rr) {
                        const int row = r0 + rr * 8;
                        const int mq  = row >> 4;
                        const int bb  = row >> 13;
                        const int jj  = g_idx[row];
                        const float2 qa = *(const float2*)(g_QK + (size_t)mq * AH_ + c0);
                        const float2 ka = *(const float2*)(g_QK + (size_t)(M1 + bb * N_ + jj) * AH_ + c0);
                        float x0 = ((rr == 0) ? v0 : v2) + qa.x - ka.x;
                        float x1 = ((rr == 0) ? v1 : v3) + qa.y - ka.y;
                        x0 = fmaxf(x0, 0.f); x1 = fmaxf(x1, 0.f);
                        *(float2*)(C + (size_t)row * AH_ + c0) = make_float2(x0, x1);
                    }
                } else {
                    const int cp = c0 - AH_;
                    *(float2*)(C2 + (size_t)r0 * D_ + cp)       = make_float2(v0, v1);
                    *(float2*)(C2 + (size_t)(r0 + 8) * D_ + cp) = make_float2(v2, v3);
                }
            } else {
                *(float2*)(C + (size_t)r0 * N + c0)       = make_float2(v0, v1);
                *(float2*)(C + (size_t)(r0 + 8) * N + c0) = make_float2(v2, v3);
            }
        }
    }
}

// ---------------------------------------------------------------------------
// finalize: per-channel softmax over k + weighted sum (VG built inline).
// ---------------------------------------------------------------------------
__global__ void finalize_kernel(float* __restrict__ out) {
    __shared__ float ss[K_][D_ + 1];
    __shared__ float sv[K_][D_ + 1];
    const int m = blockIdx.x;
    const int b = m >> 9;
    const int i = m & (N_ - 1);
    const int tid = threadIdx.x;   // 128

    for (int t = tid; t < K_ * D_; t += blockDim.x) {
        const int kk = t >> 7, d = t & (D_ - 1);
        const int row = m * K_ + kk;
        const int j = g_idx[row];
        ss[kk][d] = g_SIM[(size_t)row * D_ + d];
        sv[kk][d] = g_qkv[(size_t)(b * N_ + j) * 384 + 256 + d] + g_PE[(size_t)row * D_ + d];
    }
    __syncthreads();

    const int d = tid;
    float mx = -3.4e38f;
#pragma unroll
    for (int kk = 0; kk < K_; ++kk) mx = fmaxf(mx, ss[kk][d]);
    float s = 0.f, agg = 0.f;
#pragma unroll
    for (int kk = 0; kk < K_; ++kk) {
        const float e = expf(ss[kk][d] - mx);
        s += e;
        agg = fmaf(e, sv[kk][d], agg);
    }
    out[(size_t)b * D_ * N_ + (size_t)d * N_ + i] = agg / s;
}

// ---------------------------------------------------------------------------
// Launch
// ---------------------------------------------------------------------------
extern "C" void kernel_launch(void* const* d_in, const int* in_sizes, int n_in,
                              void* d_out, int out_size) {
    const float* x    = (const float*)d_in[0];
    const float* pos  = (const float*)d_in[1];
    const float* wqkv = (const float*)d_in[2];
    const float* pw1  = (const float*)d_in[3];
    const float* pb1  = (const float*)d_in[4];
    const float* pw2  = (const float*)d_in[5];
    const float* pb2  = (const float*)d_in[6];
    const float* aw1  = (const float*)d_in[7];
    const float* ab1  = (const float*)d_in[8];
    const float* aw2  = (const float*)d_in[9];
    const float* ab2  = (const float*)d_in[10];
    float* out = (float*)d_out;

    void *pQKV = nullptr, *pHID = nullptr, *pQK = nullptr, *pWc = nullptr,
         *pBc = nullptr, *pPE = nullptr, *pA = nullptr, *pS = nullptr;
    cudaGetSymbolAddress(&pQKV, g_qkv);
    cudaGetSymbolAddress(&pHID, g_hid);
    cudaGetSymbolAddress(&pQK,  g_QK);
    cudaGetSymbolAddress(&pWc,  g_Wc);
    cudaGetSymbolAddress(&pBc,  g_bc);
    cudaGetSymbolAddress(&pPE,  g_PE);
    cudaGetSymbolAddress(&pA,   g_A);
    cudaGetSymbolAddress(&pS,   g_SIM);

    qkv_kernel<<<M1, 128>>>(x, wqkv);
    knn_kernel<<<M1 / 8, 256>>>(pos);
    hid_kernel<<<M1, 128>>>(pos, pw1, pb1);
    prep_w_kernel<<<(PH_ * NC_ + NC_ + 255) / 256, 256>>>(pw2, pb2, aw1, ab1);
    // QA/KA = {q,k} @ aw1   (rows 0..1023 q, 1024..2047 k)
    tc_gemm<1, false><<<dim3(AH_ / 128, 16), 256>>>(
        (const float*)pQKV, aw1, nullptr, (float*)pQK, nullptr, 2 * M1, AH_, D_);
    // [A | PE] = hid @ Wc + bc  (A-cols get QA-KA gather + relu)
    tc_gemm<2, true><<<dim3(NC_ / 128, M2 / 128), 256>>>(
        (const float*)pHID, (const float*)pWc, (const float*)pBc,
        (float*)pA, (float*)pPE, M2, NC_, PH_);
    // SIM = A @ aw2 + ab2
    tc_gemm<0, true><<<dim3(1, M2 / 128), 256>>>(
        (const float*)pA, aw2, ab2, (float*)pS, nullptr, M2, D_, AH_);
    finalize_kernel<<<M1, 128>>>(out);
}